// round 9
// baseline (speedup 1.0000x reference)
#include <cuda_runtime.h>
#include <cuda_bf16.h>
#include <cstddef>

// ---------------------------------------------------------------------------
// Model_53901839564895: CNN forward
//   x [512,3,128,128]
//   conv1 5x5 pad1 (3->5) -> relu -> BN(eval) -> maxpool 3,2,1   -> [512,5,63,63]
//   conv2 3x3 pad1 (5->9) -> relu -> maxpool 3,2,1               -> [512,9,32,32]
//   conv3 3x3 pad1 (9->16) -> flatten -> FC(16384->6) -> softmax
// Weight layout quirk: effective weight = raw buffer indexed as
//   w[((c*KH+ki)*KW+kj)*COUT + o]
// R9: K1 frozen (226us, occ 72%). K2 -> (192,7). K3 -> 512 threads,
//     channel-split (two halves of 8 couts) for 2x warps at same FMA.
// ---------------------------------------------------------------------------

#define BATCH 512

// Static scratch: p1 [512,5,63,63], p2 [512,9,32,32]
__device__ float g_p1[(size_t)BATCH * 5 * 63 * 63];
__device__ float g_p2[(size_t)BATCH * 9 * 32 * 32];

// ===========================================================================
// K1: conv1(5x5,pad1)+relu+BN+maxpool(3,2,1). UNCHANGED from R8 (proven).
// ===========================================================================
__global__ __launch_bounds__(192, 7) void k1_conv_bn_pool(
    const float* __restrict__ x, const float* __restrict__ k1,
    const float* __restrict__ gamma, const float* __restrict__ beta)
{
    __shared__ float sw[375];            // 5x5x3x5
    __shared__ float sscale[5], sbeta[5];
    __shared__ float sin[3][21][37];     // input halo: 17 conv rows + 4
    __shared__ float sconv[5][17][33];   // post-BN conv tile (0 where pad)

    const int tid = threadIdx.x;
    const int b   = blockIdx.z;
    const int px0 = blockIdx.x * 16;
    const int py0 = blockIdx.y * 8;
    const int cy0 = 2 * py0 - 1;         // conv-row origin (pool pad 1)
    const int cx0 = 2 * px0 - 1;

    for (int i = tid; i < 375; i += 192) sw[i] = k1[i];
    if (tid < 5) {
        sscale[tid] = gamma[tid] * rsqrtf(1.0f + 1e-5f);
        sbeta[tid]  = beta[tid];
    }

    const float* xb = x + (size_t)b * 3 * 128 * 128;
    for (int idx = tid; idx < 3 * 21 * 37; idx += 192) {
        int c = idx / (21 * 37);
        int r = idx % (21 * 37);
        int li = r / 37, lj = r % 37;
        int iy = cy0 - 1 + li, ix = cx0 - 1 + lj;
        float v = 0.0f;
        if (iy >= 0 && iy < 128 && ix >= 0 && ix < 128)
            v = xb[(c * 128 + iy) * 128 + ix];
        sin[c][li][lj] = v;
    }
    __syncthreads();

    if (tid < 187) {
        const int y  = tid / 11;
        const int x0 = (tid % 11) * 3;

        float acc[3][5];
        #pragma unroll
        for (int xi = 0; xi < 3; xi++)
            #pragma unroll
            for (int o = 0; o < 5; o++) acc[xi][o] = 0.0f;

        #pragma unroll
        for (int c = 0; c < 3; c++) {
            #pragma unroll
            for (int ki = 0; ki < 5; ki++) {
                float r[7];
                #pragma unroll
                for (int j = 0; j < 7; j++) r[j] = sin[c][y + ki][x0 + j];
                #pragma unroll
                for (int kj = 0; kj < 5; kj++) {
                    const float* wp = &sw[((c * 5 + ki) * 5 + kj) * 5];
                    #pragma unroll
                    for (int o = 0; o < 5; o++) {
                        float wv = wp[o];
                        acc[0][o] = fmaf(r[kj],     wv, acc[0][o]);
                        acc[1][o] = fmaf(r[kj + 1], wv, acc[1][o]);
                        acc[2][o] = fmaf(r[kj + 2], wv, acc[2][o]);
                    }
                }
            }
        }
        const int cy = cy0 + y;
        const bool yok = (cy >= 0 && cy < 126);
        #pragma unroll
        for (int xi = 0; xi < 3; xi++) {
            int cx = cx0 + x0 + xi;
            bool ok = yok && (cx >= 0) && (cx < 126);
            #pragma unroll
            for (int o = 0; o < 5; o++) {
                float v = 0.0f;  // zero pool-pad matches reference
                if (ok) v = fmaf(fmaxf(acc[xi][o], 0.0f), sscale[o], sbeta[o]);
                sconv[o][y][x0 + xi] = v;
            }
        }
    }
    __syncthreads();

    float* p1b = g_p1 + (size_t)b * 5 * 63 * 63;
    for (int idx = tid; idx < 5 * 128; idx += 192) {
        int o = idx >> 7, rem = idx & 127;
        int ly = rem >> 4, lx = rem & 15;
        int py = py0 + ly, px = px0 + lx;
        if (py < 63 && px < 63) {
            float m = -1e30f;
            #pragma unroll
            for (int dy = 0; dy < 3; dy++)
                #pragma unroll
                for (int dx = 0; dx < 3; dx++)
                    m = fmaxf(m, sconv[o][2 * ly + dy][2 * lx + dx]);
            p1b[(o * 63 + py) * 63 + px] = m;
        }
    }
}

// ===========================================================================
// K2: conv2(3x3,pad1, 5->9)+relu+maxpool(3,2,1): 63x63 -> 32x32.
// R9: launch_bounds(192,7) occupancy bump (K1's proven lever).
// grid (2,4,512).
// ===========================================================================
__global__ __launch_bounds__(192, 7) void k2_conv_pool(const float* __restrict__ k2)
{
    __shared__ float sw[405];            // 3x3x5x9
    __shared__ float sin[5][19][35];     // 17 conv rows + 2 halo
    __shared__ float sconv[9][17][33];

    const int tid = threadIdx.x;
    const int b   = blockIdx.z;
    const int px0 = blockIdx.x * 16;
    const int py0 = blockIdx.y * 8;
    const int cy0 = 2 * py0 - 1;
    const int cx0 = 2 * px0 - 1;

    for (int i = tid; i < 405; i += 192) sw[i] = k2[i];

    const float* pin = g_p1 + (size_t)b * 5 * 63 * 63;
    for (int idx = tid; idx < 5 * 19 * 35; idx += 192) {
        int c = idx / (19 * 35);
        int r = idx % (19 * 35);
        int li = r / 35, lj = r % 35;
        int iy = cy0 - 1 + li, ix = cx0 - 1 + lj;
        float v = 0.0f;
        if (iy >= 0 && iy < 63 && ix >= 0 && ix < 63)
            v = pin[(c * 63 + iy) * 63 + ix];
        sin[c][li][lj] = v;
    }
    __syncthreads();

    if (tid < 187) {
        const int y  = tid / 11;
        const int x0 = (tid % 11) * 3;

        float acc[3][9];
        #pragma unroll
        for (int xi = 0; xi < 3; xi++)
            #pragma unroll
            for (int o = 0; o < 9; o++) acc[xi][o] = 0.0f;

        #pragma unroll
        for (int c = 0; c < 5; c++) {
            #pragma unroll
            for (int ki = 0; ki < 3; ki++) {
                float r[5];
                #pragma unroll
                for (int j = 0; j < 5; j++) r[j] = sin[c][y + ki][x0 + j];
                #pragma unroll
                for (int kj = 0; kj < 3; kj++) {
                    const float* wp = &sw[((c * 3 + ki) * 3 + kj) * 9];
                    #pragma unroll
                    for (int o = 0; o < 9; o++) {
                        float wv = wp[o];
                        acc[0][o] = fmaf(r[kj],     wv, acc[0][o]);
                        acc[1][o] = fmaf(r[kj + 1], wv, acc[1][o]);
                        acc[2][o] = fmaf(r[kj + 2], wv, acc[2][o]);
                    }
                }
            }
        }
        const int cy = cy0 + y;
        const bool yok = (cy >= 0 && cy < 63);
        #pragma unroll
        for (int xi = 0; xi < 3; xi++) {
            int cx = cx0 + x0 + xi;
            bool ok = yok && (cx >= 0) && (cx < 63);
            #pragma unroll
            for (int o = 0; o < 9; o++) {
                float v = 0.0f;
                if (ok) v = fmaxf(acc[xi][o], 0.0f);
                sconv[o][y][x0 + xi] = v;
            }
        }
    }
    __syncthreads();

    float* p2b = g_p2 + (size_t)b * 9 * 32 * 32;
    for (int idx = tid; idx < 9 * 128; idx += 192) {
        int o = idx >> 7, rem = idx & 127;
        int ly = rem >> 4, lx = rem & 15;
        int py = py0 + ly, px = px0 + lx;   // always < 32
        float m = -1e30f;
        #pragma unroll
        for (int dy = 0; dy < 3; dy++)
            #pragma unroll
            for (int dx = 0; dx < 3; dx++)
                m = fmaxf(m, sconv[o][2 * ly + dy][2 * lx + dx]);
        p2b[(o * 32 + py) * 32 + px] = m;
    }
}

// ===========================================================================
// K3: conv3(3x3,pad1, 9->16) + FC(16384->6) + softmax. One block per image.
// R9: 512 threads, output channels split into two halves of 8:
//   tid = half*256 + y*8 + xg ; thread owns 4 x-positions x 8 couts.
// cacc 32 regs (was 64) -> ~55 regs -> 2 CTAs/SM = 32 warps (was 16).
// grid (512), block 512.
// ===========================================================================
__global__ __launch_bounds__(512, 2) void k3_conv_fc_softmax(
    const float* __restrict__ k3, const float* __restrict__ fc_w,
    const float* __restrict__ fc_b, float* __restrict__ out)
{
    __shared__ __align__(16) float sin[9 * 32 * 32];   // 9216
    __shared__ float sw[1296];           // 3x3x9x16
    __shared__ float sred[16 * 6];
    __shared__ float slog[6];

    const int tid = threadIdx.x;
    const int b   = blockIdx.x;

    // Vectorized stage: 9216 floats = 2304 float4
    const float4* pin4 = reinterpret_cast<const float4*>(g_p2 + (size_t)b * 9 * 1024);
    float4* sin4 = reinterpret_cast<float4*>(sin);
    for (int idx = tid; idx < 2304; idx += 512) sin4[idx] = pin4[idx];
    for (int idx = tid; idx < 1296; idx += 512) sw[idx] = k3[idx];
    __syncthreads();

    const int half = tid >> 8;           // 0/1 -> couts [0,8) or [8,16)
    const int rem  = tid & 255;
    const int y    = rem >> 3;
    const int x0   = (rem & 7) * 4;
    const int obase = half * 8;

    float cacc[4][8];
    #pragma unroll
    for (int xi = 0; xi < 4; xi++)
        #pragma unroll
        for (int o = 0; o < 8; o++) cacc[xi][o] = 0.0f;

    for (int c = 0; c < 9; c++) {
        #pragma unroll
        for (int ki = 0; ki < 3; ki++) {
            int iy = y + ki - 1;
            float r[6];
            #pragma unroll
            for (int j = 0; j < 6; j++) {
                int ix = x0 - 1 + j;
                r[j] = (iy >= 0 && iy < 32 && ix >= 0 && ix < 32)
                           ? sin[(c * 32 + iy) * 32 + ix] : 0.0f;
            }
            #pragma unroll
            for (int kj = 0; kj < 3; kj++) {
                const float* wp = &sw[((c * 3 + ki) * 3 + kj) * 16 + obase];
                #pragma unroll
                for (int o = 0; o < 8; o++) {
                    float wv = wp[o];
                    #pragma unroll
                    for (int xi = 0; xi < 4; xi++)
                        cacc[xi][o] = fmaf(r[xi + kj], wv, cacc[xi][o]);
                }
            }
        }
    }

    // FC: flat index f = (obase+o)*1024 + y*32 + x0 + xi
    float facc[6];
    #pragma unroll
    for (int j = 0; j < 6; j++) facc[j] = 0.0f;
    const int base = obase * 1024 + y * 32 + x0;
    #pragma unroll
    for (int j = 0; j < 6; j++) {
        const float* wj = fc_w + (size_t)j * 16384 + base;
        #pragma unroll
        for (int o = 0; o < 8; o++) {
            float4 w4 = *reinterpret_cast<const float4*>(wj + o * 1024);
            facc[j] = fmaf(cacc[0][o], w4.x,
                      fmaf(cacc[1][o], w4.y,
                      fmaf(cacc[2][o], w4.z,
                      fmaf(cacc[3][o], w4.w, facc[j]))));
        }
    }

    #pragma unroll
    for (int j = 0; j < 6; j++) {
        float v = facc[j];
        #pragma unroll
        for (int off = 16; off > 0; off >>= 1)
            v += __shfl_down_sync(0xffffffffu, v, off);
        if ((tid & 31) == 0) sred[(tid >> 5) * 6 + j] = v;
    }
    __syncthreads();
    if (tid < 6) {
        float s = fc_b[tid];
        #pragma unroll
        for (int w = 0; w < 16; w++) s += sred[w * 6 + tid];
        slog[tid] = s;
    }
    __syncthreads();
    if (tid == 0) {
        float mx = slog[0];
        #pragma unroll
        for (int j = 1; j < 6; j++) mx = fmaxf(mx, slog[j]);
        float e[6], s = 0.0f;
        #pragma unroll
        for (int j = 0; j < 6; j++) { e[j] = expf(slog[j] - mx); s += e[j]; }
        float inv = 1.0f / s;
        #pragma unroll
        for (int j = 0; j < 6; j++) out[b * 6 + j] = e[j] * inv;
    }
}

// ===========================================================================
extern "C" void kernel_launch(void* const* d_in, const int* in_sizes, int n_in,
                              void* d_out, int out_size)
{
    const float* x     = (const float*)d_in[0];
    const float* k1    = (const float*)d_in[1];
    const float* gamma = (const float*)d_in[2];
    const float* beta  = (const float*)d_in[3];
    const float* k2    = (const float*)d_in[4];
    const float* k3    = (const float*)d_in[5];
    const float* fc_w  = (const float*)d_in[6];
    const float* fc_b  = (const float*)d_in[7];
    float* out = (float*)d_out;

    k1_conv_bn_pool<<<dim3(4, 8, BATCH), 192>>>(x, k1, gamma, beta);
    k2_conv_pool<<<dim3(2, 4, BATCH), 192>>>(k2);
    k3_conv_fc_softmax<<<BATCH, 512>>>(k3, fc_w, fc_b, out);
}

// round 10
// speedup vs baseline: 1.0650x; 1.0650x over previous
#include <cuda_runtime.h>
#include <cuda_bf16.h>
#include <cstddef>

// ---------------------------------------------------------------------------
// Model_53901839564895: CNN forward
//   x [512,3,128,128]
//   conv1 5x5 pad1 (3->5) -> relu -> BN(eval) -> maxpool 3,2,1   -> [512,5,63,63]
//   conv2 3x3 pad1 (5->9) -> relu -> maxpool 3,2,1               -> [512,9,32,32]
//   conv3 3x3 pad1 (9->16) -> flatten -> FC(16384->6) -> softmax
// Weight layout quirk: effective weight = raw buffer indexed as
//   w[((c*KH+ki)*KW+kj)*COUT + o]
// R10 = R8 structure + vectorized weight LDS (padded smem weight layout):
//   K1 375->150 weight loads/thread, K2 405->135, K3 2304->576.
// ---------------------------------------------------------------------------

#define BATCH 512

// Static scratch: p1 [512,5,63,63], p2 [512,9,32,32]
__device__ float g_p1[(size_t)BATCH * 5 * 63 * 63];
__device__ float g_p2[(size_t)BATCH * 9 * 32 * 32];

// ===========================================================================
// K1: conv1(5x5,pad1)+relu+BN+maxpool(3,2,1). R8 tiling (192 thr, 7 CTAs/SM),
// weights in smem padded 5->8 per tap group for LDS.128+LDS.32 loads.
// grid (4,8,512).
// ===========================================================================
__global__ __launch_bounds__(192, 7) void k1_conv_bn_pool(
    const float* __restrict__ x, const float* __restrict__ k1,
    const float* __restrict__ gamma, const float* __restrict__ beta)
{
    __shared__ __align__(16) float sw8[75 * 8];  // 75 tap groups x (5 couts pad 8)
    __shared__ float sscale[5], sbeta[5];
    __shared__ float sin[3][21][37];     // input halo: 17 conv rows + 4
    __shared__ float sconv[5][17][33];   // post-BN conv tile (0 where pad)

    const int tid = threadIdx.x;
    const int b   = blockIdx.z;
    const int px0 = blockIdx.x * 16;
    const int py0 = blockIdx.y * 8;
    const int cy0 = 2 * py0 - 1;         // conv-row origin (pool pad 1)
    const int cx0 = 2 * px0 - 1;

    for (int i = tid; i < 375; i += 192) {
        int g = i / 5, o = i % 5;
        sw8[g * 8 + o] = k1[i];
    }
    if (tid < 5) {
        sscale[tid] = gamma[tid] * rsqrtf(1.0f + 1e-5f);
        sbeta[tid]  = beta[tid];
    }

    const float* xb = x + (size_t)b * 3 * 128 * 128;
    for (int idx = tid; idx < 3 * 21 * 37; idx += 192) {
        int c = idx / (21 * 37);
        int r = idx % (21 * 37);
        int li = r / 37, lj = r % 37;
        int iy = cy0 - 1 + li, ix = cx0 - 1 + lj;
        float v = 0.0f;
        if (iy >= 0 && iy < 128 && ix >= 0 && ix < 128)
            v = xb[(c * 128 + iy) * 128 + ix];
        sin[c][li][lj] = v;
    }
    __syncthreads();

    if (tid < 187) {
        const int y  = tid / 11;
        const int x0 = (tid % 11) * 3;

        float acc[3][5];
        #pragma unroll
        for (int xi = 0; xi < 3; xi++)
            #pragma unroll
            for (int o = 0; o < 5; o++) acc[xi][o] = 0.0f;

        #pragma unroll
        for (int c = 0; c < 3; c++) {
            #pragma unroll
            for (int ki = 0; ki < 5; ki++) {
                float r[7];
                #pragma unroll
                for (int j = 0; j < 7; j++) r[j] = sin[c][y + ki][x0 + j];
                #pragma unroll
                for (int kj = 0; kj < 5; kj++) {
                    const int gb = ((c * 5 + ki) * 5 + kj) * 8;
                    float4 w4 = *reinterpret_cast<const float4*>(&sw8[gb]);
                    float  w5 = sw8[gb + 4];
                    float wv[5] = {w4.x, w4.y, w4.z, w4.w, w5};
                    #pragma unroll
                    for (int o = 0; o < 5; o++) {
                        acc[0][o] = fmaf(r[kj],     wv[o], acc[0][o]);
                        acc[1][o] = fmaf(r[kj + 1], wv[o], acc[1][o]);
                        acc[2][o] = fmaf(r[kj + 2], wv[o], acc[2][o]);
                    }
                }
            }
        }
        const int cy = cy0 + y;
        const bool yok = (cy >= 0 && cy < 126);
        #pragma unroll
        for (int xi = 0; xi < 3; xi++) {
            int cx = cx0 + x0 + xi;
            bool ok = yok && (cx >= 0) && (cx < 126);
            #pragma unroll
            for (int o = 0; o < 5; o++) {
                float v = 0.0f;  // zero pool-pad matches reference
                if (ok) v = fmaf(fmaxf(acc[xi][o], 0.0f), sscale[o], sbeta[o]);
                sconv[o][y][x0 + xi] = v;
            }
        }
    }
    __syncthreads();

    float* p1b = g_p1 + (size_t)b * 5 * 63 * 63;
    for (int idx = tid; idx < 5 * 128; idx += 192) {
        int o = idx >> 7, rem = idx & 127;
        int ly = rem >> 4, lx = rem & 15;
        int py = py0 + ly, px = px0 + lx;
        if (py < 63 && px < 63) {
            float m = -1e30f;
            #pragma unroll
            for (int dy = 0; dy < 3; dy++)
                #pragma unroll
                for (int dx = 0; dx < 3; dx++)
                    m = fmaxf(m, sconv[o][2 * ly + dy][2 * lx + dx]);
            p1b[(o * 63 + py) * 63 + px] = m;
        }
    }
}

// ===========================================================================
// K2: conv2(3x3,pad1, 5->9)+relu+maxpool(3,2,1): 63x63 -> 32x32.
// R8 bound (192,6); weights padded 9->12 per tap group (48B aligned):
// 2x LDS.128 + 1x LDS.32 per group. grid (2,4,512).
// ===========================================================================
__global__ __launch_bounds__(192, 6) void k2_conv_pool(const float* __restrict__ k2)
{
    __shared__ __align__(16) float sw12[45 * 12]; // 45 tap groups x (9 pad 12)
    __shared__ float sin[5][19][35];     // 17 conv rows + 2 halo
    __shared__ float sconv[9][17][33];

    const int tid = threadIdx.x;
    const int b   = blockIdx.z;
    const int px0 = blockIdx.x * 16;
    const int py0 = blockIdx.y * 8;
    const int cy0 = 2 * py0 - 1;
    const int cx0 = 2 * px0 - 1;

    for (int i = tid; i < 405; i += 192) {
        int g = i / 9, o = i % 9;
        sw12[g * 12 + o] = k2[i];
    }

    const float* pin = g_p1 + (size_t)b * 5 * 63 * 63;
    for (int idx = tid; idx < 5 * 19 * 35; idx += 192) {
        int c = idx / (19 * 35);
        int r = idx % (19 * 35);
        int li = r / 35, lj = r % 35;
        int iy = cy0 - 1 + li, ix = cx0 - 1 + lj;
        float v = 0.0f;
        if (iy >= 0 && iy < 63 && ix >= 0 && ix < 63)
            v = pin[(c * 63 + iy) * 63 + ix];
        sin[c][li][lj] = v;
    }
    __syncthreads();

    if (tid < 187) {
        const int y  = tid / 11;
        const int x0 = (tid % 11) * 3;

        float acc[3][9];
        #pragma unroll
        for (int xi = 0; xi < 3; xi++)
            #pragma unroll
            for (int o = 0; o < 9; o++) acc[xi][o] = 0.0f;

        #pragma unroll
        for (int c = 0; c < 5; c++) {
            #pragma unroll
            for (int ki = 0; ki < 3; ki++) {
                float r[5];
                #pragma unroll
                for (int j = 0; j < 5; j++) r[j] = sin[c][y + ki][x0 + j];
                #pragma unroll
                for (int kj = 0; kj < 3; kj++) {
                    const int gb = ((c * 3 + ki) * 3 + kj) * 12;
                    float4 wa = *reinterpret_cast<const float4*>(&sw12[gb]);
                    float4 wb = *reinterpret_cast<const float4*>(&sw12[gb + 4]);
                    float  w8 = sw12[gb + 8];
                    float wv[9] = {wa.x, wa.y, wa.z, wa.w,
                                   wb.x, wb.y, wb.z, wb.w, w8};
                    #pragma unroll
                    for (int o = 0; o < 9; o++) {
                        acc[0][o] = fmaf(r[kj],     wv[o], acc[0][o]);
                        acc[1][o] = fmaf(r[kj + 1], wv[o], acc[1][o]);
                        acc[2][o] = fmaf(r[kj + 2], wv[o], acc[2][o]);
                    }
                }
            }
        }
        const int cy = cy0 + y;
        const bool yok = (cy >= 0 && cy < 63);
        #pragma unroll
        for (int xi = 0; xi < 3; xi++) {
            int cx = cx0 + x0 + xi;
            bool ok = yok && (cx >= 0) && (cx < 63);
            #pragma unroll
            for (int o = 0; o < 9; o++) {
                float v = 0.0f;
                if (ok) v = fmaxf(acc[xi][o], 0.0f);
                sconv[o][y][x0 + xi] = v;
            }
        }
    }
    __syncthreads();

    float* p2b = g_p2 + (size_t)b * 9 * 32 * 32;
    for (int idx = tid; idx < 9 * 128; idx += 192) {
        int o = idx >> 7, rem = idx & 127;
        int ly = rem >> 4, lx = rem & 15;
        int py = py0 + ly, px = px0 + lx;   // always < 32
        float m = -1e30f;
        #pragma unroll
        for (int dy = 0; dy < 3; dy++)
            #pragma unroll
            for (int dx = 0; dx < 3; dx++)
                m = fmaxf(m, sconv[o][2 * ly + dy][2 * lx + dx]);
        p2b[(o * 32 + py) * 32 + px] = m;
    }
}

// ===========================================================================
// K3: conv3(3x3,pad1, 9->16) + FC(16384->6) + softmax. R8 shape (256 thr,
// 2 CTAs/SM); weight groups [g][16] are 64B aligned -> 4x LDS.128 per group.
// grid (512), block 256.
// ===========================================================================
__global__ __launch_bounds__(256, 2) void k3_conv_fc_softmax(
    const float* __restrict__ k3, const float* __restrict__ fc_w,
    const float* __restrict__ fc_b, float* __restrict__ out)
{
    __shared__ __align__(16) float sin[9 * 32 * 32];   // 9216
    __shared__ __align__(16) float sw[1296];           // 3x3x9x16, groups 64B aligned
    __shared__ float sred[8 * 6];
    __shared__ float slog[6];

    const int tid = threadIdx.x;
    const int b   = blockIdx.x;

    const float4* pin4 = reinterpret_cast<const float4*>(g_p2 + (size_t)b * 9 * 1024);
    float4* sin4 = reinterpret_cast<float4*>(sin);
    for (int idx = tid; idx < 2304; idx += 256) sin4[idx] = pin4[idx];
    for (int idx = tid; idx < 1296; idx += 256) sw[idx] = k3[idx];
    __syncthreads();

    const int y  = tid >> 3;
    const int x0 = (tid & 7) * 4;

    float cacc[4][16];
    #pragma unroll
    for (int xi = 0; xi < 4; xi++)
        #pragma unroll
        for (int o = 0; o < 16; o++) cacc[xi][o] = 0.0f;

    for (int c = 0; c < 9; c++) {
        #pragma unroll
        for (int ki = 0; ki < 3; ki++) {
            int iy = y + ki - 1;
            float r[6];
            #pragma unroll
            for (int j = 0; j < 6; j++) {
                int ix = x0 - 1 + j;
                r[j] = (iy >= 0 && iy < 32 && ix >= 0 && ix < 32)
                           ? sin[(c * 32 + iy) * 32 + ix] : 0.0f;
            }
            #pragma unroll
            for (int kj = 0; kj < 3; kj++) {
                const float* wp = &sw[((c * 3 + ki) * 3 + kj) * 16];
                #pragma unroll
                for (int q = 0; q < 4; q++) {
                    float4 w4 = *reinterpret_cast<const float4*>(wp + q * 4);
                    float wv[4] = {w4.x, w4.y, w4.z, w4.w};
                    #pragma unroll
                    for (int t = 0; t < 4; t++) {
                        int o = q * 4 + t;
                        #pragma unroll
                        for (int xi = 0; xi < 4; xi++)
                            cacc[xi][o] = fmaf(r[xi + kj], wv[t], cacc[xi][o]);
                    }
                }
            }
        }
    }

    // FC: flat index f = o*1024 + y*32 + x0 + xi
    float facc[6];
    #pragma unroll
    for (int j = 0; j < 6; j++) facc[j] = 0.0f;
    const int base = y * 32 + x0;
    #pragma unroll
    for (int j = 0; j < 6; j++) {
        const float* wj = fc_w + (size_t)j * 16384 + base;
        #pragma unroll
        for (int o = 0; o < 16; o++) {
            float4 w4 = *reinterpret_cast<const float4*>(wj + o * 1024);
            facc[j] = fmaf(cacc[0][o], w4.x,
                      fmaf(cacc[1][o], w4.y,
                      fmaf(cacc[2][o], w4.z,
                      fmaf(cacc[3][o], w4.w, facc[j]))));
        }
    }

    #pragma unroll
    for (int j = 0; j < 6; j++) {
        float v = facc[j];
        #pragma unroll
        for (int off = 16; off > 0; off >>= 1)
            v += __shfl_down_sync(0xffffffffu, v, off);
        if ((tid & 31) == 0) sred[(tid >> 5) * 6 + j] = v;
    }
    __syncthreads();
    if (tid < 6) {
        float s = fc_b[tid];
        #pragma unroll
        for (int w = 0; w < 8; w++) s += sred[w * 6 + tid];
        slog[tid] = s;
    }
    __syncthreads();
    if (tid == 0) {
        float mx = slog[0];
        #pragma unroll
        for (int j = 1; j < 6; j++) mx = fmaxf(mx, slog[j]);
        float e[6], s = 0.0f;
        #pragma unroll
        for (int j = 0; j < 6; j++) { e[j] = expf(slog[j] - mx); s += e[j]; }
        float inv = 1.0f / s;
        #pragma unroll
        for (int j = 0; j < 6; j++) out[b * 6 + j] = e[j] * inv;
    }
}

// ===========================================================================
extern "C" void kernel_launch(void* const* d_in, const int* in_sizes, int n_in,
                              void* d_out, int out_size)
{
    const float* x     = (const float*)d_in[0];
    const float* k1    = (const float*)d_in[1];
    const float* gamma = (const float*)d_in[2];
    const float* beta  = (const float*)d_in[3];
    const float* k2    = (const float*)d_in[4];
    const float* k3    = (const float*)d_in[5];
    const float* fc_w  = (const float*)d_in[6];
    const float* fc_b  = (const float*)d_in[7];
    float* out = (float*)d_out;

    k1_conv_bn_pool<<<dim3(4, 8, BATCH), 192>>>(x, k1, gamma, beta);
    k2_conv_pool<<<dim3(2, 4, BATCH), 192>>>(k2);
    k3_conv_fc_softmax<<<BATCH, 256>>>(k3, fc_w, fc_b, out);
}

// round 11
// speedup vs baseline: 1.0918x; 1.0252x over previous
#include <cuda_runtime.h>
#include <cuda_bf16.h>
#include <cstddef>

// ---------------------------------------------------------------------------
// Model_53901839564895: CNN forward
//   x [512,3,128,128]
//   conv1 5x5 pad1 (3->5) -> relu -> BN(eval) -> maxpool 3,2,1   -> [512,5,63,63]
//   conv2 3x3 pad1 (5->9) -> relu -> maxpool 3,2,1               -> [512,9,32,32]
//   conv3 3x3 pad1 (9->16) -> flatten -> FC(16384->6) -> softmax
// Weight layout quirk: effective weight = raw buffer indexed as
//   w[((c*KH+ki)*KW+kj)*COUT + o]
// R11 = R8 (best: 355.6us) + cheap-index halo loaders (no per-element div/mod)
// ---------------------------------------------------------------------------

#define BATCH 512

// Static scratch: p1 [512,5,63,63], p2 [512,9,32,32]
__device__ float g_p1[(size_t)BATCH * 5 * 63 * 63];
__device__ float g_p2[(size_t)BATCH * 9 * 32 * 32];

// ===========================================================================
// K1: conv1(5x5,pad1)+relu+BN+maxpool(3,2,1). R8 tiling: 192 thr, 7 CTAs/SM,
// 187 conv items (y 0..16, x-groups of 3), one item per thread.
// Halo loader: fixed column per thread, stride-5 rows, compare-add channel.
// grid (4,8,512).
// ===========================================================================
__global__ __launch_bounds__(192, 7) void k1_conv_bn_pool(
    const float* __restrict__ x, const float* __restrict__ k1,
    const float* __restrict__ gamma, const float* __restrict__ beta)
{
    __shared__ float sw[375];            // 5x5x3x5
    __shared__ float sscale[5], sbeta[5];
    __shared__ float sin[3][21][37];     // input halo: 17 conv rows + 4
    __shared__ float sconv[5][17][33];   // post-BN conv tile (0 where pad)

    const int tid = threadIdx.x;
    const int b   = blockIdx.z;
    const int px0 = blockIdx.x * 16;
    const int py0 = blockIdx.y * 8;
    const int cy0 = 2 * py0 - 1;         // conv-row origin (pool pad 1)
    const int cx0 = 2 * px0 - 1;

    for (int i = tid; i < 375; i += 192) sw[i] = k1[i];
    if (tid < 5) {
        sscale[tid] = gamma[tid] * rsqrtf(1.0f + 1e-5f);
        sbeta[tid]  = beta[tid];
    }

    // Halo: 63 rows (3ch x 21) x 37 cols. Thread owns column tj, rows
    // rg, rg+5, ... (threads 185..191 idle here). Channel from row by
    // compare-add; no div/mod in the loop.
    const float* xb = x + (size_t)b * 3 * 128 * 128;
    if (tid < 185) {
        const int tj = tid % 37;
        const int rg = tid / 37;          // 0..4
        const int ix = cx0 - 1 + tj;
        const bool xok = (ix >= 0 && ix < 128);
        #pragma unroll 1
        for (int row = rg; row < 63; row += 5) {
            int c  = (row >= 21) + (row >= 42);
            int li = row - c * 21;
            int iy = cy0 - 1 + li;
            float v = 0.0f;
            if (xok && iy >= 0 && iy < 128)
                v = xb[(c * 128 + iy) * 128 + ix];
            sin[c][li][tj] = v;
        }
    }
    __syncthreads();

    if (tid < 187) {
        const int y  = tid / 11;
        const int x0 = (tid % 11) * 3;

        float acc[3][5];
        #pragma unroll
        for (int xi = 0; xi < 3; xi++)
            #pragma unroll
            for (int o = 0; o < 5; o++) acc[xi][o] = 0.0f;

        #pragma unroll
        for (int c = 0; c < 3; c++) {
            #pragma unroll
            for (int ki = 0; ki < 5; ki++) {
                float r[7];
                #pragma unroll
                for (int j = 0; j < 7; j++) r[j] = sin[c][y + ki][x0 + j];
                #pragma unroll
                for (int kj = 0; kj < 5; kj++) {
                    const float* wp = &sw[((c * 5 + ki) * 5 + kj) * 5];
                    #pragma unroll
                    for (int o = 0; o < 5; o++) {
                        float wv = wp[o];
                        acc[0][o] = fmaf(r[kj],     wv, acc[0][o]);
                        acc[1][o] = fmaf(r[kj + 1], wv, acc[1][o]);
                        acc[2][o] = fmaf(r[kj + 2], wv, acc[2][o]);
                    }
                }
            }
        }
        const int cy = cy0 + y;
        const bool yok = (cy >= 0 && cy < 126);
        #pragma unroll
        for (int xi = 0; xi < 3; xi++) {
            int cx = cx0 + x0 + xi;
            bool ok = yok && (cx >= 0) && (cx < 126);
            #pragma unroll
            for (int o = 0; o < 5; o++) {
                float v = 0.0f;  // zero pool-pad matches reference
                if (ok) v = fmaf(fmaxf(acc[xi][o], 0.0f), sscale[o], sbeta[o]);
                sconv[o][y][x0 + xi] = v;
            }
        }
    }
    __syncthreads();

    float* p1b = g_p1 + (size_t)b * 5 * 63 * 63;
    for (int idx = tid; idx < 5 * 128; idx += 192) {
        int o = idx >> 7, rem = idx & 127;
        int ly = rem >> 4, lx = rem & 15;
        int py = py0 + ly, px = px0 + lx;
        if (py < 63 && px < 63) {
            float m = -1e30f;
            #pragma unroll
            for (int dy = 0; dy < 3; dy++)
                #pragma unroll
                for (int dx = 0; dx < 3; dx++)
                    m = fmaxf(m, sconv[o][2 * ly + dy][2 * lx + dx]);
            p1b[(o * 63 + py) * 63 + px] = m;
        }
    }
}

// ===========================================================================
// K2: conv2(3x3,pad1, 5->9)+relu+maxpool(3,2,1): 63x63 -> 32x32.
// R8 bound (192,6); cheap-index halo loader. grid (2,4,512).
// ===========================================================================
__global__ __launch_bounds__(192, 6) void k2_conv_pool(const float* __restrict__ k2)
{
    __shared__ float sw[405];            // 3x3x5x9
    __shared__ float sin[5][19][35];     // 17 conv rows + 2 halo
    __shared__ float sconv[9][17][33];

    const int tid = threadIdx.x;
    const int b   = blockIdx.z;
    const int px0 = blockIdx.x * 16;
    const int py0 = blockIdx.y * 8;
    const int cy0 = 2 * py0 - 1;
    const int cx0 = 2 * px0 - 1;

    for (int i = tid; i < 405; i += 192) sw[i] = k2[i];

    // Halo: 95 rows (5ch x 19) x 35 cols. Thread owns column tj, stride-5
    // rows (threads 175..191 idle here). Channel via compare-add.
    const float* pin = g_p1 + (size_t)b * 5 * 63 * 63;
    if (tid < 175) {
        const int tj = tid % 35;
        const int rg = tid / 35;          // 0..4
        const int ix = cx0 - 1 + tj;
        const bool xok = (ix >= 0 && ix < 63);
        #pragma unroll 1
        for (int row = rg; row < 95; row += 5) {
            int c  = (row >= 19) + (row >= 38) + (row >= 57) + (row >= 76);
            int li = row - c * 19;
            int iy = cy0 - 1 + li;
            float v = 0.0f;
            if (xok && iy >= 0 && iy < 63)
                v = pin[(c * 63 + iy) * 63 + ix];
            sin[c][li][tj] = v;
        }
    }
    __syncthreads();

    if (tid < 187) {
        const int y  = tid / 11;
        const int x0 = (tid % 11) * 3;

        float acc[3][9];
        #pragma unroll
        for (int xi = 0; xi < 3; xi++)
            #pragma unroll
            for (int o = 0; o < 9; o++) acc[xi][o] = 0.0f;

        #pragma unroll
        for (int c = 0; c < 5; c++) {
            #pragma unroll
            for (int ki = 0; ki < 3; ki++) {
                float r[5];
                #pragma unroll
                for (int j = 0; j < 5; j++) r[j] = sin[c][y + ki][x0 + j];
                #pragma unroll
                for (int kj = 0; kj < 3; kj++) {
                    const float* wp = &sw[((c * 3 + ki) * 3 + kj) * 9];
                    #pragma unroll
                    for (int o = 0; o < 9; o++) {
                        float wv = wp[o];
                        acc[0][o] = fmaf(r[kj],     wv, acc[0][o]);
                        acc[1][o] = fmaf(r[kj + 1], wv, acc[1][o]);
                        acc[2][o] = fmaf(r[kj + 2], wv, acc[2][o]);
                    }
                }
            }
        }
        const int cy = cy0 + y;
        const bool yok = (cy >= 0 && cy < 63);
        #pragma unroll
        for (int xi = 0; xi < 3; xi++) {
            int cx = cx0 + x0 + xi;
            bool ok = yok && (cx >= 0) && (cx < 63);
            #pragma unroll
            for (int o = 0; o < 9; o++) {
                float v = 0.0f;
                if (ok) v = fmaxf(acc[xi][o], 0.0f);
                sconv[o][y][x0 + xi] = v;
            }
        }
    }
    __syncthreads();

    float* p2b = g_p2 + (size_t)b * 9 * 32 * 32;
    for (int idx = tid; idx < 9 * 128; idx += 192) {
        int o = idx >> 7, rem = idx & 127;
        int ly = rem >> 4, lx = rem & 15;
        int py = py0 + ly, px = px0 + lx;   // always < 32
        float m = -1e30f;
        #pragma unroll
        for (int dy = 0; dy < 3; dy++)
            #pragma unroll
            for (int dx = 0; dx < 3; dx++)
                m = fmaxf(m, sconv[o][2 * ly + dy][2 * lx + dx]);
        p2b[(o * 32 + py) * 32 + px] = m;
    }
}

// ===========================================================================
// K3: conv3(3x3,pad1, 9->16) + FC(16384->6) + softmax. R8 version.
// grid (512), block 256, 2 CTAs/SM.
// ===========================================================================
__global__ __launch_bounds__(256, 2) void k3_conv_fc_softmax(
    const float* __restrict__ k3, const float* __restrict__ fc_w,
    const float* __restrict__ fc_b, float* __restrict__ out)
{
    __shared__ __align__(16) float sin[9 * 32 * 32];   // 9216
    __shared__ float sw[1296];           // 3x3x9x16
    __shared__ float sred[8 * 6];
    __shared__ float slog[6];

    const int tid = threadIdx.x;
    const int b   = blockIdx.x;

    const float4* pin4 = reinterpret_cast<const float4*>(g_p2 + (size_t)b * 9 * 1024);
    float4* sin4 = reinterpret_cast<float4*>(sin);
    for (int idx = tid; idx < 2304; idx += 256) sin4[idx] = pin4[idx];
    for (int idx = tid; idx < 1296; idx += 256) sw[idx] = k3[idx];
    __syncthreads();

    const int y  = tid >> 3;
    const int x0 = (tid & 7) * 4;

    float cacc[4][16];
    #pragma unroll
    for (int xi = 0; xi < 4; xi++)
        #pragma unroll
        for (int o = 0; o < 16; o++) cacc[xi][o] = 0.0f;

    for (int c = 0; c < 9; c++) {
        #pragma unroll
        for (int ki = 0; ki < 3; ki++) {
            int iy = y + ki - 1;
            float r[6];
            #pragma unroll
            for (int j = 0; j < 6; j++) {
                int ix = x0 - 1 + j;
                r[j] = (iy >= 0 && iy < 32 && ix >= 0 && ix < 32)
                           ? sin[(c * 32 + iy) * 32 + ix] : 0.0f;
            }
            #pragma unroll
            for (int kj = 0; kj < 3; kj++) {
                const float* wp = &sw[((c * 3 + ki) * 3 + kj) * 16];
                #pragma unroll
                for (int o = 0; o < 16; o++) {
                    float wv = wp[o];
                    #pragma unroll
                    for (int xi = 0; xi < 4; xi++)
                        cacc[xi][o] = fmaf(r[xi + kj], wv, cacc[xi][o]);
                }
            }
        }
    }

    // FC: flat index f = o*1024 + y*32 + x0 + xi
    float facc[6];
    #pragma unroll
    for (int j = 0; j < 6; j++) facc[j] = 0.0f;
    const int base = y * 32 + x0;
    #pragma unroll
    for (int j = 0; j < 6; j++) {
        const float* wj = fc_w + (size_t)j * 16384 + base;
        #pragma unroll
        for (int o = 0; o < 16; o++) {
            float4 w4 = *reinterpret_cast<const float4*>(wj + o * 1024);
            facc[j] = fmaf(cacc[0][o], w4.x,
                      fmaf(cacc[1][o], w4.y,
                      fmaf(cacc[2][o], w4.z,
                      fmaf(cacc[3][o], w4.w, facc[j]))));
        }
    }

    #pragma unroll
    for (int j = 0; j < 6; j++) {
        float v = facc[j];
        #pragma unroll
        for (int off = 16; off > 0; off >>= 1)
            v += __shfl_down_sync(0xffffffffu, v, off);
        if ((tid & 31) == 0) sred[(tid >> 5) * 6 + j] = v;
    }
    __syncthreads();
    if (tid < 6) {
        float s = fc_b[tid];
        #pragma unroll
        for (int w = 0; w < 8; w++) s += sred[w * 6 + tid];
        slog[tid] = s;
    }
    __syncthreads();
    if (tid == 0) {
        float mx = slog[0];
        #pragma unroll
        for (int j = 1; j < 6; j++) mx = fmaxf(mx, slog[j]);
        float e[6], s = 0.0f;
        #pragma unroll
        for (int j = 0; j < 6; j++) { e[j] = expf(slog[j] - mx); s += e[j]; }
        float inv = 1.0f / s;
        #pragma unroll
        for (int j = 0; j < 6; j++) out[b * 6 + j] = e[j] * inv;
    }
}

// ===========================================================================
extern "C" void kernel_launch(void* const* d_in, const int* in_sizes, int n_in,
                              void* d_out, int out_size)
{
    const float* x     = (const float*)d_in[0];
    const float* k1    = (const float*)d_in[1];
    const float* gamma = (const float*)d_in[2];
    const float* beta  = (const float*)d_in[3];
    const float* k2    = (const float*)d_in[4];
    const float* k3    = (const float*)d_in[5];
    const float* fc_w  = (const float*)d_in[6];
    const float* fc_b  = (const float*)d_in[7];
    float* out = (float*)d_out;

    k1_conv_bn_pool<<<dim3(4, 8, BATCH), 192>>>(x, k1, gamma, beta);
    k2_conv_pool<<<dim3(2, 4, BATCH), 192>>>(k2);
    k3_conv_fc_softmax<<<BATCH, 256>>>(k3, fc_w, fc_b, out);
}

// round 12
// speedup vs baseline: 1.1932x; 1.0928x over previous
#include <cuda_runtime.h>
#include <cuda_bf16.h>
#include <cstddef>

// ---------------------------------------------------------------------------
// Model_53901839564895: CNN forward
//   conv1 5x5 pad1 (3->5) -> relu -> BN(eval) -> maxpool 3,2,1   -> [512,5,63,63]
//   conv2 3x3 pad1 (5->9) -> relu -> maxpool 3,2,1               -> [512,9,32,32]
//   conv3 3x3 pad1 (9->16) -> flatten -> FC(16384->6) -> softmax
// conv3 has NO activation -> conv3+FC is one linear map. R12 folds them:
//   W_eff[j, c,iy,ix] = sum_{o,ki,kj} k3_eff * fc_w[j, o*1024+(iy+1-ki)*32+(ix+1-kj)]
//   logits = p2 . W_eff + b   (deletes conv3's 679M MACs)
// Weight layout quirk: effective conv weight = raw buffer indexed as
//   w[((c*KH+ki)*KW+kj)*COUT + o]
// ---------------------------------------------------------------------------

#define BATCH 512

// Static scratch
__device__ float g_p1[(size_t)BATCH * 5 * 63 * 63];
__device__ float g_p2[(size_t)BATCH * 9 * 32 * 32];
__device__ float g_weff[6 * 9216];   // folded conv3+FC weights

// ===========================================================================
// K1: conv1+relu+BN+maxpool. UNCHANGED from R11 (216us, fma 44.8%).
// ===========================================================================
__global__ __launch_bounds__(192, 7) void k1_conv_bn_pool(
    const float* __restrict__ x, const float* __restrict__ k1,
    const float* __restrict__ gamma, const float* __restrict__ beta)
{
    __shared__ float sw[375];
    __shared__ float sscale[5], sbeta[5];
    __shared__ float sin[3][21][37];
    __shared__ float sconv[5][17][33];

    const int tid = threadIdx.x;
    const int b   = blockIdx.z;
    const int px0 = blockIdx.x * 16;
    const int py0 = blockIdx.y * 8;
    const int cy0 = 2 * py0 - 1;
    const int cx0 = 2 * px0 - 1;

    for (int i = tid; i < 375; i += 192) sw[i] = k1[i];
    if (tid < 5) {
        sscale[tid] = gamma[tid] * rsqrtf(1.0f + 1e-5f);
        sbeta[tid]  = beta[tid];
    }

    const float* xb = x + (size_t)b * 3 * 128 * 128;
    if (tid < 185) {
        const int tj = tid % 37;
        const int rg = tid / 37;
        const int ix = cx0 - 1 + tj;
        const bool xok = (ix >= 0 && ix < 128);
        #pragma unroll 1
        for (int row = rg; row < 63; row += 5) {
            int c  = (row >= 21) + (row >= 42);
            int li = row - c * 21;
            int iy = cy0 - 1 + li;
            float v = 0.0f;
            if (xok && iy >= 0 && iy < 128)
                v = xb[(c * 128 + iy) * 128 + ix];
            sin[c][li][tj] = v;
        }
    }
    __syncthreads();

    if (tid < 187) {
        const int y  = tid / 11;
        const int x0 = (tid % 11) * 3;

        float acc[3][5];
        #pragma unroll
        for (int xi = 0; xi < 3; xi++)
            #pragma unroll
            for (int o = 0; o < 5; o++) acc[xi][o] = 0.0f;

        #pragma unroll
        for (int c = 0; c < 3; c++) {
            #pragma unroll
            for (int ki = 0; ki < 5; ki++) {
                float r[7];
                #pragma unroll
                for (int j = 0; j < 7; j++) r[j] = sin[c][y + ki][x0 + j];
                #pragma unroll
                for (int kj = 0; kj < 5; kj++) {
                    const float* wp = &sw[((c * 5 + ki) * 5 + kj) * 5];
                    #pragma unroll
                    for (int o = 0; o < 5; o++) {
                        float wv = wp[o];
                        acc[0][o] = fmaf(r[kj],     wv, acc[0][o]);
                        acc[1][o] = fmaf(r[kj + 1], wv, acc[1][o]);
                        acc[2][o] = fmaf(r[kj + 2], wv, acc[2][o]);
                    }
                }
            }
        }
        const int cy = cy0 + y;
        const bool yok = (cy >= 0 && cy < 126);
        #pragma unroll
        for (int xi = 0; xi < 3; xi++) {
            int cx = cx0 + x0 + xi;
            bool ok = yok && (cx >= 0) && (cx < 126);
            #pragma unroll
            for (int o = 0; o < 5; o++) {
                float v = 0.0f;
                if (ok) v = fmaf(fmaxf(acc[xi][o], 0.0f), sscale[o], sbeta[o]);
                sconv[o][y][x0 + xi] = v;
            }
        }
    }
    __syncthreads();

    float* p1b = g_p1 + (size_t)b * 5 * 63 * 63;
    for (int idx = tid; idx < 5 * 128; idx += 192) {
        int o = idx >> 7, rem = idx & 127;
        int ly = rem >> 4, lx = rem & 15;
        int py = py0 + ly, px = px0 + lx;
        if (py < 63 && px < 63) {
            float m = -1e30f;
            #pragma unroll
            for (int dy = 0; dy < 3; dy++)
                #pragma unroll
                for (int dx = 0; dx < 3; dx++)
                    m = fmaxf(m, sconv[o][2 * ly + dy][2 * lx + dx]);
            p1b[(o * 63 + py) * 63 + px] = m;
        }
    }
}

// ===========================================================================
// K2: conv2+relu+maxpool. UNCHANGED from R11. grid (2,4,512).
// ===========================================================================
__global__ __launch_bounds__(192, 6) void k2_conv_pool(const float* __restrict__ k2)
{
    __shared__ float sw[405];
    __shared__ float sin[5][19][35];
    __shared__ float sconv[9][17][33];

    const int tid = threadIdx.x;
    const int b   = blockIdx.z;
    const int px0 = blockIdx.x * 16;
    const int py0 = blockIdx.y * 8;
    const int cy0 = 2 * py0 - 1;
    const int cx0 = 2 * px0 - 1;

    for (int i = tid; i < 405; i += 192) sw[i] = k2[i];

    const float* pin = g_p1 + (size_t)b * 5 * 63 * 63;
    if (tid < 175) {
        const int tj = tid % 35;
        const int rg = tid / 35;
        const int ix = cx0 - 1 + tj;
        const bool xok = (ix >= 0 && ix < 63);
        #pragma unroll 1
        for (int row = rg; row < 95; row += 5) {
            int c  = (row >= 19) + (row >= 38) + (row >= 57) + (row >= 76);
            int li = row - c * 19;
            int iy = cy0 - 1 + li;
            float v = 0.0f;
            if (xok && iy >= 0 && iy < 63)
                v = pin[(c * 63 + iy) * 63 + ix];
            sin[c][li][tj] = v;
        }
    }
    __syncthreads();

    if (tid < 187) {
        const int y  = tid / 11;
        const int x0 = (tid % 11) * 3;

        float acc[3][9];
        #pragma unroll
        for (int xi = 0; xi < 3; xi++)
            #pragma unroll
            for (int o = 0; o < 9; o++) acc[xi][o] = 0.0f;

        #pragma unroll
        for (int c = 0; c < 5; c++) {
            #pragma unroll
            for (int ki = 0; ki < 3; ki++) {
                float r[5];
                #pragma unroll
                for (int j = 0; j < 5; j++) r[j] = sin[c][y + ki][x0 + j];
                #pragma unroll
                for (int kj = 0; kj < 3; kj++) {
                    const float* wp = &sw[((c * 3 + ki) * 3 + kj) * 9];
                    #pragma unroll
                    for (int o = 0; o < 9; o++) {
                        float wv = wp[o];
                        acc[0][o] = fmaf(r[kj],     wv, acc[0][o]);
                        acc[1][o] = fmaf(r[kj + 1], wv, acc[1][o]);
                        acc[2][o] = fmaf(r[kj + 2], wv, acc[2][o]);
                    }
                }
            }
        }
        const int cy = cy0 + y;
        const bool yok = (cy >= 0 && cy < 63);
        #pragma unroll
        for (int xi = 0; xi < 3; xi++) {
            int cx = cx0 + x0 + xi;
            bool ok = yok && (cx >= 0) && (cx < 63);
            #pragma unroll
            for (int o = 0; o < 9; o++) {
                float v = 0.0f;
                if (ok) v = fmaxf(acc[xi][o], 0.0f);
                sconv[o][y][x0 + xi] = v;
            }
        }
    }
    __syncthreads();

    float* p2b = g_p2 + (size_t)b * 9 * 32 * 32;
    for (int idx = tid; idx < 9 * 128; idx += 192) {
        int o = idx >> 7, rem = idx & 127;
        int ly = rem >> 4, lx = rem & 15;
        int py = py0 + ly, px = px0 + lx;
        float m = -1e30f;
        #pragma unroll
        for (int dy = 0; dy < 3; dy++)
            #pragma unroll
            for (int dx = 0; dx < 3; dx++)
                m = fmaxf(m, sconv[o][2 * ly + dy][2 * lx + dx]);
        p2b[(o * 32 + py) * 32 + px] = m;
    }
}

// ===========================================================================
// K3a: fold conv3 into FC. W_eff[j, c*1024+iy*32+ix] =
//   sum_{o,ki,kj, 0<=iy+1-ki<32, 0<=ix+1-kj<32}
//     k3[((c*3+ki)*3+kj)*16+o] * fc_w[j*16384 + o*1024 + (iy+1-ki)*32 + (ix+1-kj)]
// 6*9216 = 55296 outputs. grid 216, block 256.
// ===========================================================================
__global__ __launch_bounds__(256) void k3a_fold(
    const float* __restrict__ k3, const float* __restrict__ fc_w)
{
    __shared__ float sk[1296];
    const int tid = threadIdx.x;
    for (int i = tid; i < 1296; i += 256) sk[i] = k3[i];
    __syncthreads();

    int idx = blockIdx.x * 256 + tid;
    if (idx >= 6 * 9216) return;
    const int j   = idx / 9216;
    const int rem = idx % 9216;
    const int c   = rem >> 10;
    const int iy  = (rem & 1023) >> 5;
    const int ix  = rem & 31;

    const float* wj = fc_w + (size_t)j * 16384;
    float s = 0.0f;
    #pragma unroll
    for (int ki = 0; ki < 3; ki++) {
        int y = iy + 1 - ki;
        if (y < 0 || y >= 32) continue;
        #pragma unroll
        for (int kj = 0; kj < 3; kj++) {
            int xx = ix + 1 - kj;
            if (xx < 0 || xx >= 32) continue;
            const float* kp = &sk[((c * 3 + ki) * 3 + kj) * 16];
            const float* fp = wj + y * 32 + xx;
            #pragma unroll
            for (int o = 0; o < 16; o++)
                s = fmaf(kp[o], fp[o * 1024], s);
        }
    }
    g_weff[idx] = s;
}

// ===========================================================================
// K3b: logits = p2 . W_eff^T + b, softmax. One block per image, 256 threads.
// Thread t handles float4 elements t, t+256, ... (9 per thread) against all
// 6 W_eff rows. W_eff (221KB) stays L2-resident across 512 blocks.
// ===========================================================================
__global__ __launch_bounds__(256) void k3b_gemv_softmax(
    const float* __restrict__ fc_b, float* __restrict__ out)
{
    __shared__ float sred[8 * 6];
    __shared__ float slog[6];

    const int tid = threadIdx.x;
    const int b   = blockIdx.x;

    const float4* a4 = reinterpret_cast<const float4*>(g_p2 + (size_t)b * 9216);
    const float4* w4 = reinterpret_cast<const float4*>(g_weff);

    float acc[6];
    #pragma unroll
    for (int j = 0; j < 6; j++) acc[j] = 0.0f;

    #pragma unroll 1
    for (int i = tid; i < 2304; i += 256) {
        float4 a = a4[i];
        #pragma unroll
        for (int j = 0; j < 6; j++) {
            float4 w = w4[j * 2304 + i];
            acc[j] = fmaf(a.x, w.x, fmaf(a.y, w.y,
                     fmaf(a.z, w.z, fmaf(a.w, w.w, acc[j]))));
        }
    }

    #pragma unroll
    for (int j = 0; j < 6; j++) {
        float v = acc[j];
        #pragma unroll
        for (int off = 16; off > 0; off >>= 1)
            v += __shfl_down_sync(0xffffffffu, v, off);
        if ((tid & 31) == 0) sred[(tid >> 5) * 6 + j] = v;
    }
    __syncthreads();
    if (tid < 6) {
        float s = fc_b[tid];
        #pragma unroll
        for (int w = 0; w < 8; w++) s += sred[w * 6 + tid];
        slog[tid] = s;
    }
    __syncthreads();
    if (tid == 0) {
        float mx = slog[0];
        #pragma unroll
        for (int j = 1; j < 6; j++) mx = fmaxf(mx, slog[j]);
        float e[6], s = 0.0f;
        #pragma unroll
        for (int j = 0; j < 6; j++) { e[j] = expf(slog[j] - mx); s += e[j]; }
        float inv = 1.0f / s;
        #pragma unroll
        for (int j = 0; j < 6; j++) out[b * 6 + j] = e[j] * inv;
    }
}

// ===========================================================================
extern "C" void kernel_launch(void* const* d_in, const int* in_sizes, int n_in,
                              void* d_out, int out_size)
{
    const float* x     = (const float*)d_in[0];
    const float* k1    = (const float*)d_in[1];
    const float* gamma = (const float*)d_in[2];
    const float* beta  = (const float*)d_in[3];
    const float* k2    = (const float*)d_in[4];
    const float* k3    = (const float*)d_in[5];
    const float* fc_w  = (const float*)d_in[6];
    const float* fc_b  = (const float*)d_in[7];
    float* out = (float*)d_out;

    k1_conv_bn_pool<<<dim3(4, 8, BATCH), 192>>>(x, k1, gamma, beta);
    k3a_fold<<<216, 256>>>(k3, fc_w);          // independent of K1/K2; overlaps
    k2_conv_pool<<<dim3(2, 4, BATCH), 192>>>(k2);
    k3b_gemv_softmax<<<BATCH, 256>>>(fc_b, out);
}

// round 13
// speedup vs baseline: 1.2030x; 1.0082x over previous
#include <cuda_runtime.h>
#include <cuda_bf16.h>
#include <cstddef>

// ---------------------------------------------------------------------------
// Model_53901839564895: CNN forward
//   conv1 5x5 pad1 (3->5) -> relu -> BN(eval) -> maxpool 3,2,1   -> [512,5,63,63]
//   conv2 3x3 pad1 (5->9) -> relu -> maxpool 3,2,1               -> (fused out)
//   conv3 3x3 pad1 (9->16) -> flatten -> FC(16384->6) -> softmax
// conv3+FC folded into W_eff (R12). R13: GEMV fused INTO K2's pool phase —
// p2 never exists; K2 blocks emit per-block partial logits (deterministic,
// no atomics), k3c reduces 8 partials/image + softmax.
// Weight layout quirk: effective conv weight = raw buffer indexed as
//   w[((c*KH+ki)*KW+kj)*COUT + o]
// ---------------------------------------------------------------------------

#define BATCH 512

// Static scratch
__device__ float g_p1[(size_t)BATCH * 5 * 63 * 63];
__device__ float g_weff[6 * 9216];              // folded conv3+FC weights
__device__ float g_part[(size_t)BATCH * 8 * 6]; // per-K2-block partial logits

// ===========================================================================
// K1: conv1+relu+BN+maxpool. UNCHANGED from R11 (216us, ~90% of FFMA floor).
// ===========================================================================
__global__ __launch_bounds__(192, 7) void k1_conv_bn_pool(
    const float* __restrict__ x, const float* __restrict__ k1,
    const float* __restrict__ gamma, const float* __restrict__ beta)
{
    __shared__ float sw[375];
    __shared__ float sscale[5], sbeta[5];
    __shared__ float sin[3][21][37];
    __shared__ float sconv[5][17][33];

    const int tid = threadIdx.x;
    const int b   = blockIdx.z;
    const int px0 = blockIdx.x * 16;
    const int py0 = blockIdx.y * 8;
    const int cy0 = 2 * py0 - 1;
    const int cx0 = 2 * px0 - 1;

    for (int i = tid; i < 375; i += 192) sw[i] = k1[i];
    if (tid < 5) {
        sscale[tid] = gamma[tid] * rsqrtf(1.0f + 1e-5f);
        sbeta[tid]  = beta[tid];
    }

    const float* xb = x + (size_t)b * 3 * 128 * 128;
    if (tid < 185) {
        const int tj = tid % 37;
        const int rg = tid / 37;
        const int ix = cx0 - 1 + tj;
        const bool xok = (ix >= 0 && ix < 128);
        #pragma unroll 1
        for (int row = rg; row < 63; row += 5) {
            int c  = (row >= 21) + (row >= 42);
            int li = row - c * 21;
            int iy = cy0 - 1 + li;
            float v = 0.0f;
            if (xok && iy >= 0 && iy < 128)
                v = xb[(c * 128 + iy) * 128 + ix];
            sin[c][li][tj] = v;
        }
    }
    __syncthreads();

    if (tid < 187) {
        const int y  = tid / 11;
        const int x0 = (tid % 11) * 3;

        float acc[3][5];
        #pragma unroll
        for (int xi = 0; xi < 3; xi++)
            #pragma unroll
            for (int o = 0; o < 5; o++) acc[xi][o] = 0.0f;

        #pragma unroll
        for (int c = 0; c < 3; c++) {
            #pragma unroll
            for (int ki = 0; ki < 5; ki++) {
                float r[7];
                #pragma unroll
                for (int j = 0; j < 7; j++) r[j] = sin[c][y + ki][x0 + j];
                #pragma unroll
                for (int kj = 0; kj < 5; kj++) {
                    const float* wp = &sw[((c * 5 + ki) * 5 + kj) * 5];
                    #pragma unroll
                    for (int o = 0; o < 5; o++) {
                        float wv = wp[o];
                        acc[0][o] = fmaf(r[kj],     wv, acc[0][o]);
                        acc[1][o] = fmaf(r[kj + 1], wv, acc[1][o]);
                        acc[2][o] = fmaf(r[kj + 2], wv, acc[2][o]);
                    }
                }
            }
        }
        const int cy = cy0 + y;
        const bool yok = (cy >= 0 && cy < 126);
        #pragma unroll
        for (int xi = 0; xi < 3; xi++) {
            int cx = cx0 + x0 + xi;
            bool ok = yok && (cx >= 0) && (cx < 126);
            #pragma unroll
            for (int o = 0; o < 5; o++) {
                float v = 0.0f;
                if (ok) v = fmaf(fmaxf(acc[xi][o], 0.0f), sscale[o], sbeta[o]);
                sconv[o][y][x0 + xi] = v;
            }
        }
    }
    __syncthreads();

    float* p1b = g_p1 + (size_t)b * 5 * 63 * 63;
    for (int idx = tid; idx < 5 * 128; idx += 192) {
        int o = idx >> 7, rem = idx & 127;
        int ly = rem >> 4, lx = rem & 15;
        int py = py0 + ly, px = px0 + lx;
        if (py < 63 && px < 63) {
            float m = -1e30f;
            #pragma unroll
            for (int dy = 0; dy < 3; dy++)
                #pragma unroll
                for (int dx = 0; dx < 3; dx++)
                    m = fmaxf(m, sconv[o][2 * ly + dy][2 * lx + dx]);
            p1b[(o * 63 + py) * 63 + px] = m;
        }
    }
}

// ===========================================================================
// K3a: fold conv3 into FC (unchanged from R12). Runs before K2.
// ===========================================================================
__global__ __launch_bounds__(256) void k3a_fold(
    const float* __restrict__ k3, const float* __restrict__ fc_w)
{
    __shared__ float sk[1296];
    const int tid = threadIdx.x;
    for (int i = tid; i < 1296; i += 256) sk[i] = k3[i];
    __syncthreads();

    int idx = blockIdx.x * 256 + tid;
    if (idx >= 6 * 9216) return;
    const int j   = idx / 9216;
    const int rem = idx % 9216;
    const int c   = rem >> 10;
    const int iy  = (rem & 1023) >> 5;
    const int ix  = rem & 31;

    const float* wj = fc_w + (size_t)j * 16384;
    float s = 0.0f;
    #pragma unroll
    for (int ki = 0; ki < 3; ki++) {
        int y = iy + 1 - ki;
        if (y < 0 || y >= 32) continue;
        #pragma unroll
        for (int kj = 0; kj < 3; kj++) {
            int xx = ix + 1 - kj;
            if (xx < 0 || xx >= 32) continue;
            const float* kp = &sk[((c * 3 + ki) * 3 + kj) * 16];
            const float* fp = wj + y * 32 + xx;
            #pragma unroll
            for (int o = 0; o < 16; o++)
                s = fmaf(kp[o], fp[o * 1024], s);
        }
    }
    g_weff[idx] = s;
}

// ===========================================================================
// K2: conv2+relu+maxpool FUSED with the W_eff dot product. Pooled values never
// leave the block: each contributes to 6 partial logits; per-block partials
// written to g_part (deterministic). grid (2,4,512), blk id = by*2+bx.
// ===========================================================================
__global__ __launch_bounds__(192, 6) void k2_conv_pool_dot(const float* __restrict__ k2)
{
    __shared__ float sw[405];
    __shared__ float sin[5][19][35];
    __shared__ float sconv[9][17][33];
    __shared__ float sred[6][6];         // [warp][logit]

    const int tid = threadIdx.x;
    const int b   = blockIdx.z;
    const int px0 = blockIdx.x * 16;
    const int py0 = blockIdx.y * 8;
    const int cy0 = 2 * py0 - 1;
    const int cx0 = 2 * px0 - 1;

    for (int i = tid; i < 405; i += 192) sw[i] = k2[i];

    const float* pin = g_p1 + (size_t)b * 5 * 63 * 63;
    if (tid < 175) {
        const int tj = tid % 35;
        const int rg = tid / 35;
        const int ix = cx0 - 1 + tj;
        const bool xok = (ix >= 0 && ix < 63);
        #pragma unroll 1
        for (int row = rg; row < 95; row += 5) {
            int c  = (row >= 19) + (row >= 38) + (row >= 57) + (row >= 76);
            int li = row - c * 19;
            int iy = cy0 - 1 + li;
            float v = 0.0f;
            if (xok && iy >= 0 && iy < 63)
                v = pin[(c * 63 + iy) * 63 + ix];
            sin[c][li][tj] = v;
        }
    }
    __syncthreads();

    if (tid < 187) {
        const int y  = tid / 11;
        const int x0 = (tid % 11) * 3;

        float acc[3][9];
        #pragma unroll
        for (int xi = 0; xi < 3; xi++)
            #pragma unroll
            for (int o = 0; o < 9; o++) acc[xi][o] = 0.0f;

        #pragma unroll
        for (int c = 0; c < 5; c++) {
            #pragma unroll
            for (int ki = 0; ki < 3; ki++) {
                float r[5];
                #pragma unroll
                for (int j = 0; j < 5; j++) r[j] = sin[c][y + ki][x0 + j];
                #pragma unroll
                for (int kj = 0; kj < 3; kj++) {
                    const float* wp = &sw[((c * 3 + ki) * 3 + kj) * 9];
                    #pragma unroll
                    for (int o = 0; o < 9; o++) {
                        float wv = wp[o];
                        acc[0][o] = fmaf(r[kj],     wv, acc[0][o]);
                        acc[1][o] = fmaf(r[kj + 1], wv, acc[1][o]);
                        acc[2][o] = fmaf(r[kj + 2], wv, acc[2][o]);
                    }
                }
            }
        }
        const int cy = cy0 + y;
        const bool yok = (cy >= 0 && cy < 63);
        #pragma unroll
        for (int xi = 0; xi < 3; xi++) {
            int cx = cx0 + x0 + xi;
            bool ok = yok && (cx >= 0) && (cx < 63);
            #pragma unroll
            for (int o = 0; o < 9; o++) {
                float v = 0.0f;
                if (ok) v = fmaxf(acc[xi][o], 0.0f);
                sconv[o][y][x0 + xi] = v;
            }
        }
    }
    __syncthreads();

    // Pool + dot with W_eff (flat f = o*1024 + py*32 + px), 6 iters/thread
    float part[6];
    #pragma unroll
    for (int j = 0; j < 6; j++) part[j] = 0.0f;

    for (int idx = tid; idx < 9 * 128; idx += 192) {
        int o = idx >> 7, rem = idx & 127;
        int ly = rem >> 4, lx = rem & 15;
        int py = py0 + ly, px = px0 + lx;   // always < 32
        float m = -1e30f;
        #pragma unroll
        for (int dy = 0; dy < 3; dy++)
            #pragma unroll
            for (int dx = 0; dx < 3; dx++)
                m = fmaxf(m, sconv[o][2 * ly + dy][2 * lx + dx]);
        const int f = o * 1024 + py * 32 + px;
        #pragma unroll
        for (int j = 0; j < 6; j++)
            part[j] = fmaf(m, g_weff[j * 9216 + f], part[j]);
    }

    // Block reduce: 6 warps -> sred -> thread j sums column j
    #pragma unroll
    for (int j = 0; j < 6; j++) {
        float v = part[j];
        #pragma unroll
        for (int off = 16; off > 0; off >>= 1)
            v += __shfl_down_sync(0xffffffffu, v, off);
        if ((tid & 31) == 0) sred[tid >> 5][j] = v;
    }
    __syncthreads();
    if (tid < 6) {
        float s = 0.0f;
        #pragma unroll
        for (int w = 0; w < 6; w++) s += sred[w][tid];
        const int blk = blockIdx.y * 2 + blockIdx.x;   // 0..7
        g_part[((size_t)b * 8 + blk) * 6 + tid] = s;
    }
}

// ===========================================================================
// K3c: reduce 8 block-partials per image + bias, softmax. 512 threads total.
// ===========================================================================
__global__ __launch_bounds__(256) void k3c_softmax(
    const float* __restrict__ fc_b, float* __restrict__ out)
{
    const int i = blockIdx.x * 256 + threadIdx.x;
    if (i >= BATCH) return;
    const float* pp = g_part + (size_t)i * 48;
    float lg[6];
    #pragma unroll
    for (int j = 0; j < 6; j++) lg[j] = fc_b[j];
    #pragma unroll
    for (int blk = 0; blk < 8; blk++)
        #pragma unroll
        for (int j = 0; j < 6; j++) lg[j] += pp[blk * 6 + j];

    float mx = lg[0];
    #pragma unroll
    for (int j = 1; j < 6; j++) mx = fmaxf(mx, lg[j]);
    float e[6], s = 0.0f;
    #pragma unroll
    for (int j = 0; j < 6; j++) { e[j] = expf(lg[j] - mx); s += e[j]; }
    float inv = 1.0f / s;
    #pragma unroll
    for (int j = 0; j < 6; j++) out[i * 6 + j] = e[j] * inv;
}

// ===========================================================================
extern "C" void kernel_launch(void* const* d_in, const int* in_sizes, int n_in,
                              void* d_out, int out_size)
{
    const float* x     = (const float*)d_in[0];
    const float* k1    = (const float*)d_in[1];
    const float* gamma = (const float*)d_in[2];
    const float* beta  = (const float*)d_in[3];
    const float* k2    = (const float*)d_in[4];
    const float* k3    = (const float*)d_in[5];
    const float* fc_w  = (const float*)d_in[6];
    const float* fc_b  = (const float*)d_in[7];
    float* out = (float*)d_out;

    k1_conv_bn_pool<<<dim3(4, 8, BATCH), 192>>>(x, k1, gamma, beta);
    k3a_fold<<<216, 256>>>(k3, fc_w);          // W_eff ready before K2 (stream order)
    k2_conv_pool_dot<<<dim3(2, 4, BATCH), 192>>>(k2);
    k3c_softmax<<<2, 256>>>(fc_b, out);
}